// round 11
// baseline (speedup 1.0000x reference)
#include <cuda_runtime.h>
#include <cstdint>

// Spiking MLP: s2 = ((x @ W1^T >= 1) @ W2^T >= 1)
// FFMA2 (fma.rn.f32x2) SIMT GEMM, double-buffered BK=16, M-paired accumulators.
// Per-output math: ascending-k serial fp32 FMA chain — bit-identical to the
// proven round-1/round-10 kernels (rel_err 0.0).

#define NTHREADS 256

static const int M_BATCH = 4096;
static const int FEAT    = 6272;
static const int IN_DIM  = 3136;
static const int OUT_DIM = 500;

// hidden spikes scratch: 4096 * 6272 floats = 102.8 MB
__device__ float g_s1[4096ull * 6272ull];

// d(.f32x2) += a * b   (two independent IEEE fp32 FMAs, lanewise)
#define FMA2(d, a, b) \
    asm("fma.rn.f32x2 %0, %1, %2, %0;" : "+l"(d) : "l"(a), "l"(b))

__device__ __forceinline__ unsigned long long pack_dup(float x) {
    unsigned long long r;
    unsigned int u = __float_as_uint(x);
    asm("mov.b64 %0, {%1, %1};" : "=l"(r) : "r"(u));
    return r;
}

// C = threshold(A @ B^T). A [M,K] row-major, B [N,K] row-major.
// CTA tile: BM x 128, BM = 16*TM. M % BM == 0, K % 16 == 0. N may be ragged.
// acc pairs along M: acc2[i2][j] = (C[ty*TM+2i2][j], C[ty*TM+2i2+1][j]).
template <int TM>
__global__ __launch_bounds__(NTHREADS, 2)
void spike_gemm2x_kernel(const float* __restrict__ A,
                         const float* __restrict__ B,
                         float* __restrict__ C,
                         int N, int K)
{
    constexpr int BM = 16 * TM;
    __shared__ float As[2][16][BM];
    __shared__ float Bs[2][16][128];

    const int tid = threadIdx.x;
    const int tx  = tid % 16;           // N group (8 cols)
    const int ty  = tid / 16;           // M group (TM rows)
    const int m0  = blockIdx.y * BM;
    const int n0  = blockIdx.x * 128;

    // ---- staging maps ----
    // B: 128 rows x 16 k -> thread: row tid>>1, k-half (tid&1)*8 (2 float4)
    const int lrB = tid >> 1;
    const int lcB = (tid & 1) * 8;
    const bool   brow_ok = (n0 + lrB) < N;
    const float* Bptr = B + (size_t)(n0 + lrB) * K + lcB;

    // A: BM rows x 16 k
    //   TM==8: row tid>>1, k-half (tid&1)*8  (2 float4)
    //   TM==4: row tid>>2, k-quarter (tid&3)*4 (1 float4)
    const int lrA = (TM == 8) ? (tid >> 1) : (tid >> 2);
    const int lcA = (TM == 8) ? ((tid & 1) * 8) : ((tid & 3) * 4);
    const float* Aptr = A + (size_t)(m0 + lrA) * K + lcA;

    unsigned long long acc2[TM / 2][8];
#pragma unroll
    for (int i = 0; i < TM / 2; i++)
#pragma unroll
        for (int j = 0; j < 8; j++) acc2[i][j] = 0ull;

    float4 av0, av1, bv0, bv1;

    // ---- prologue: load chunk 0, stage into buf 0 ----
    av0 = *(const float4*)(Aptr);
    if (TM == 8) av1 = *(const float4*)(Aptr + 4);
    bv0 = brow_ok ? *(const float4*)(Bptr)     : make_float4(0.f, 0.f, 0.f, 0.f);
    bv1 = brow_ok ? *(const float4*)(Bptr + 4) : make_float4(0.f, 0.f, 0.f, 0.f);
    {
        As[0][lcA + 0][lrA] = av0.x;
        As[0][lcA + 1][lrA] = av0.y;
        As[0][lcA + 2][lrA] = av0.z;
        As[0][lcA + 3][lrA] = av0.w;
        if (TM == 8) {
            As[0][lcA + 4][lrA] = av1.x;
            As[0][lcA + 5][lrA] = av1.y;
            As[0][lcA + 6][lrA] = av1.z;
            As[0][lcA + 7][lrA] = av1.w;
        }
        Bs[0][lcB + 0][lrB] = bv0.x;
        Bs[0][lcB + 1][lrB] = bv0.y;
        Bs[0][lcB + 2][lrB] = bv0.z;
        Bs[0][lcB + 3][lrB] = bv0.w;
        Bs[0][lcB + 4][lrB] = bv1.x;
        Bs[0][lcB + 5][lrB] = bv1.y;
        Bs[0][lcB + 6][lrB] = bv1.z;
        Bs[0][lcB + 7][lrB] = bv1.w;
    }
    __syncthreads();

    const int NITER = K >> 4;
    for (int it = 0; it < NITER; it++) {
        const int buf = it & 1;
        const int k0  = it << 4;

        // prefetch next chunk into registers (covers gmem latency with compute)
        const bool more = (it + 1 < NITER);
        if (more) {
            av0 = *(const float4*)(Aptr + k0 + 16);
            if (TM == 8) av1 = *(const float4*)(Aptr + k0 + 20);
            bv0 = brow_ok ? *(const float4*)(Bptr + k0 + 16) : make_float4(0.f, 0.f, 0.f, 0.f);
            bv1 = brow_ok ? *(const float4*)(Bptr + k0 + 20) : make_float4(0.f, 0.f, 0.f, 0.f);
        }

        // ---- compute 16 k-steps from buf ----
#pragma unroll
        for (int kk = 0; kk < 16; kk++) {
            // a pairs: consecutive M floats read directly as packed f32x2
            unsigned long long a2[TM / 2];
            if (TM == 8) {
                ulonglong2 q0 = *(const ulonglong2*)&As[buf][kk][ty * 8];
                ulonglong2 q1 = *(const ulonglong2*)&As[buf][kk][ty * 8 + 4];
                a2[0] = q0.x; a2[1] = q0.y; a2[2] = q1.x; a2[3] = q1.y;
            } else {
                ulonglong2 q0 = *(const ulonglong2*)&As[buf][kk][ty * 4];
                a2[0] = q0.x; a2[1] = q0.y;
            }
            float4 b0 = *(const float4*)&Bs[buf][kk][tx * 8];
            float4 b1 = *(const float4*)&Bs[buf][kk][tx * 8 + 4];
            unsigned long long bd[8];
            bd[0] = pack_dup(b0.x); bd[1] = pack_dup(b0.y);
            bd[2] = pack_dup(b0.z); bd[3] = pack_dup(b0.w);
            bd[4] = pack_dup(b1.x); bd[5] = pack_dup(b1.y);
            bd[6] = pack_dup(b1.z); bd[7] = pack_dup(b1.w);
#pragma unroll
            for (int i2 = 0; i2 < TM / 2; i2++)
#pragma unroll
                for (int j = 0; j < 8; j++)
                    FMA2(acc2[i2][j], a2[i2], bd[j]);
        }

        // ---- stage next chunk into the other buffer ----
        if (more) {
            const int nb = buf ^ 1;
            As[nb][lcA + 0][lrA] = av0.x;
            As[nb][lcA + 1][lrA] = av0.y;
            As[nb][lcA + 2][lrA] = av0.z;
            As[nb][lcA + 3][lrA] = av0.w;
            if (TM == 8) {
                As[nb][lcA + 4][lrA] = av1.x;
                As[nb][lcA + 5][lrA] = av1.y;
                As[nb][lcA + 6][lrA] = av1.z;
                As[nb][lcA + 7][lrA] = av1.w;
            }
            Bs[nb][lcB + 0][lrB] = bv0.x;
            Bs[nb][lcB + 1][lrB] = bv0.y;
            Bs[nb][lcB + 2][lrB] = bv0.z;
            Bs[nb][lcB + 3][lrB] = bv0.w;
            Bs[nb][lcB + 4][lrB] = bv1.x;
            Bs[nb][lcB + 5][lrB] = bv1.y;
            Bs[nb][lcB + 6][lrB] = bv1.z;
            Bs[nb][lcB + 7][lrB] = bv1.w;
            __syncthreads();
        }
    }

    // ---- fused threshold epilogue ----
#pragma unroll
    for (int i2 = 0; i2 < TM / 2; i2++) {
        const int row = m0 + ty * TM + 2 * i2;
#pragma unroll
        for (int j = 0; j < 8; j++) {
            const unsigned long long p = acc2[i2][j];
            const float vlo = __uint_as_float((unsigned int)(p & 0xFFFFFFFFull));
            const float vhi = __uint_as_float((unsigned int)(p >> 32));
            const int col = n0 + tx * 8 + j;
            if (col < N) {
                C[(size_t)row * N + col]       = (vlo >= 1.0f) ? 1.0f : 0.0f;
                C[(size_t)(row + 1) * N + col] = (vhi >= 1.0f) ? 1.0f : 0.0f;
            }
        }
    }
}

extern "C" void kernel_launch(void* const* d_in, const int* in_sizes, int n_in,
                              void* d_out, int out_size)
{
    const float* x  = (const float*)d_in[0];   // [4096, 3136]
    const float* W1 = (const float*)d_in[1];   // [6272, 3136]
    const float* W2 = (const float*)d_in[2];   // [500, 6272]
    float* out = (float*)d_out;                // [4096, 500]

    float* s1 = nullptr;
    cudaGetSymbolAddress((void**)&s1, g_s1);

    // GEMM1: s1 = threshold(x @ W1^T)   M=4096, N=6272, K=3136  (tile 128x128)
    {
        dim3 grid(FEAT / 128, M_BATCH / 128);  // (49, 32)
        spike_gemm2x_kernel<8><<<grid, NTHREADS>>>(x, W1, s1, FEAT, IN_DIM);
    }
    // GEMM2: out = threshold(s1 @ W2^T)  M=4096, N=500, K=6272  (tile 64x128)
    {
        dim3 grid((OUT_DIM + 127) / 128, M_BATCH / 64);  // (4, 64)
        spike_gemm2x_kernel<4><<<grid, NTHREADS>>>(s1, W2, out, OUT_DIM, FEAT);
    }
}

// round 12
// speedup vs baseline: 1.0467x; 1.0467x over previous
#include <cuda_runtime.h>
#include <cstdint>

// Spiking MLP: s2 = ((x @ W1^T >= 1) @ W2^T >= 1)
// FFMA2 SIMT GEMM, 16x8 register tile (0.375 smem-B/FLOP), double-buffered BK=16.
// Per-output math: ascending-k serial fp32 FMA chain — bit-identical to the
// proven round-1/10/11 kernels (rel_err 0.0).

static const int M_BATCH = 4096;
static const int FEAT    = 6272;
static const int IN_DIM  = 3136;
static const int OUT_DIM = 500;

// hidden spikes scratch: 4096 * 6272 floats = 102.8 MB
__device__ float g_s1[4096ull * 6272ull];

// d(.f32x2) += a * b   (two independent IEEE fp32 FMAs, lanewise)
#define FMA2(d, a, b) \
    asm("fma.rn.f32x2 %0, %1, %2, %0;" : "+l"(d) : "l"(a), "l"(b))

__device__ __forceinline__ unsigned long long pack_dup(float x) {
    unsigned long long r;
    unsigned int u = __float_as_uint(x);
    asm("mov.b64 %0, {%1, %1};" : "=l"(r) : "r"(u));
    return r;
}

// C = threshold(A @ B^T). A [M,K] row-major, B [N,K] row-major.
// CTA tile: BM x 128 with BM = THREADS, thread tile 16(M) x 8(N).
// tx = tid & 15 (8 cols each), ty = tid >> 4 (16 rows each).
// acc2[i2][j] = (C[ty*16+2*i2][j], C[ty*16+2*i2+1][j]) packed f32x2.
// M % BM == 0, K % 16 == 0. N may be ragged (guarded).
template <int THREADS>
__global__ __launch_bounds__(THREADS, 1)
void spike_gemm2x_kernel(const float* __restrict__ A,
                         const float* __restrict__ B,
                         float* __restrict__ C,
                         int N, int K)
{
    constexpr int BM = THREADS;              // 256 (gemm1) or 128 (gemm2)
    __shared__ __align__(16) float As[2][16][BM];
    __shared__ __align__(16) float Bs[2][16][128];

    const int tid = threadIdx.x;
    const int tx  = tid & 15;                // N group (8 cols)
    const int ty  = tid >> 4;                // M group (16 rows)
    const int m0  = blockIdx.y * BM;
    const int n0  = blockIdx.x * 128;

    // ---- staging maps ----
    // A: BM rows x 16 k; one full row per thread (4 float4)
    const float* Aptr = A + (size_t)(m0 + tid) * K;
    // B: 128 rows x 16 k
    //   THREADS==256: row tid>>1, k-half (tid&1)*8 (2 float4)
    //   THREADS==128: row tid, all 16 k (4 float4)
    constexpr int NB4 = (THREADS == 256) ? 2 : 4;
    const int lrB = (THREADS == 256) ? (tid >> 1) : tid;
    const int lcB = (THREADS == 256) ? ((tid & 1) * 8) : 0;
    const bool   brow_ok = (n0 + lrB) < N;
    const float* Bptr = B + (size_t)(n0 + lrB) * K + lcB;

    unsigned long long acc2[8][8];
#pragma unroll
    for (int i = 0; i < 8; i++)
#pragma unroll
        for (int j = 0; j < 8; j++) acc2[i][j] = 0ull;

    float4 av[4], bv[NB4];

    // ---- prologue: load chunk 0 ----
#pragma unroll
    for (int q = 0; q < 4; q++) av[q] = *(const float4*)(Aptr + q * 4);
#pragma unroll
    for (int q = 0; q < NB4; q++)
        bv[q] = brow_ok ? *(const float4*)(Bptr + q * 4)
                        : make_float4(0.f, 0.f, 0.f, 0.f);
    // stage into buf 0 (transposed: [k][row])
#pragma unroll
    for (int q = 0; q < 4; q++) {
        As[0][q * 4 + 0][tid] = av[q].x;
        As[0][q * 4 + 1][tid] = av[q].y;
        As[0][q * 4 + 2][tid] = av[q].z;
        As[0][q * 4 + 3][tid] = av[q].w;
    }
#pragma unroll
    for (int q = 0; q < NB4; q++) {
        Bs[0][lcB + q * 4 + 0][lrB] = bv[q].x;
        Bs[0][lcB + q * 4 + 1][lrB] = bv[q].y;
        Bs[0][lcB + q * 4 + 2][lrB] = bv[q].z;
        Bs[0][lcB + q * 4 + 3][lrB] = bv[q].w;
    }
    __syncthreads();

    const int NITER = K >> 4;
    for (int it = 0; it < NITER; it++) {
        const int buf = it & 1;
        const int kb  = (it << 4) + 16;

        // prefetch next chunk into registers (gmem latency overlaps compute)
        const bool more = (it + 1 < NITER);
        if (more) {
#pragma unroll
            for (int q = 0; q < 4; q++) av[q] = *(const float4*)(Aptr + kb + q * 4);
#pragma unroll
            for (int q = 0; q < NB4; q++)
                bv[q] = brow_ok ? *(const float4*)(Bptr + kb + q * 4)
                                : make_float4(0.f, 0.f, 0.f, 0.f);
        }

        // ---- compute 16 k-steps from buf ----
#pragma unroll
        for (int kk = 0; kk < 16; kk++) {
            // a pairs: 16 consecutive M floats = 8 packed f32x2, read direct
            ulonglong2 p0 = *(const ulonglong2*)&As[buf][kk][ty * 16];
            ulonglong2 p1 = *(const ulonglong2*)&As[buf][kk][ty * 16 + 4];
            ulonglong2 p2 = *(const ulonglong2*)&As[buf][kk][ty * 16 + 8];
            ulonglong2 p3 = *(const ulonglong2*)&As[buf][kk][ty * 16 + 12];
            unsigned long long a2[8] = {p0.x, p0.y, p1.x, p1.y,
                                        p2.x, p2.y, p3.x, p3.y};
            float4 b0 = *(const float4*)&Bs[buf][kk][tx * 8];
            float4 b1 = *(const float4*)&Bs[buf][kk][tx * 8 + 4];
            unsigned long long bd[8];
            bd[0] = pack_dup(b0.x); bd[1] = pack_dup(b0.y);
            bd[2] = pack_dup(b0.z); bd[3] = pack_dup(b0.w);
            bd[4] = pack_dup(b1.x); bd[5] = pack_dup(b1.y);
            bd[6] = pack_dup(b1.z); bd[7] = pack_dup(b1.w);
#pragma unroll
            for (int i2 = 0; i2 < 8; i2++)
#pragma unroll
                for (int j = 0; j < 8; j++)
                    FMA2(acc2[i2][j], a2[i2], bd[j]);
        }

        // ---- stage next chunk into the other buffer ----
        if (more) {
            const int nb = buf ^ 1;
            __syncthreads();   // everyone done reading buf^1 from 2 iters ago
#pragma unroll
            for (int q = 0; q < 4; q++) {
                As[nb][q * 4 + 0][tid] = av[q].x;
                As[nb][q * 4 + 1][tid] = av[q].y;
                As[nb][q * 4 + 2][tid] = av[q].z;
                As[nb][q * 4 + 3][tid] = av[q].w;
            }
#pragma unroll
            for (int q = 0; q < NB4; q++) {
                Bs[nb][lcB + q * 4 + 0][lrB] = bv[q].x;
                Bs[nb][lcB + q * 4 + 1][lrB] = bv[q].y;
                Bs[nb][lcB + q * 4 + 2][lrB] = bv[q].z;
                Bs[nb][lcB + q * 4 + 3][lrB] = bv[q].w;
            }
            __syncthreads();
        }
    }

    // ---- fused threshold epilogue ----
#pragma unroll
    for (int i2 = 0; i2 < 8; i2++) {
        const int row = m0 + ty * 16 + 2 * i2;
#pragma unroll
        for (int j = 0; j < 8; j++) {
            const unsigned long long p = acc2[i2][j];
            const float vlo = __uint_as_float((unsigned int)(p & 0xFFFFFFFFull));
            const float vhi = __uint_as_float((unsigned int)(p >> 32));
            const int col = n0 + tx * 8 + j;
            if (col < N) {
                C[(size_t)row * N + col]       = (vlo >= 1.0f) ? 1.0f : 0.0f;
                C[(size_t)(row + 1) * N + col] = (vhi >= 1.0f) ? 1.0f : 0.0f;
            }
        }
    }
}

extern "C" void kernel_launch(void* const* d_in, const int* in_sizes, int n_in,
                              void* d_out, int out_size)
{
    const float* x  = (const float*)d_in[0];   // [4096, 3136]
    const float* W1 = (const float*)d_in[1];   // [6272, 3136]
    const float* W2 = (const float*)d_in[2];   // [500, 6272]
    float* out = (float*)d_out;                // [4096, 500]

    float* s1 = nullptr;
    cudaGetSymbolAddress((void**)&s1, g_s1);

    // GEMM1: s1 = threshold(x @ W1^T)  M=4096, N=6272, K=3136  (tile 256x128)
    {
        dim3 grid(FEAT / 128, M_BATCH / 256);  // (49, 16)
        spike_gemm2x_kernel<256><<<grid, 256>>>(x, W1, s1, FEAT, IN_DIM);
    }
    // GEMM2: out = threshold(s1 @ W2^T)  M=4096, N=500, K=6272  (tile 128x128)
    {
        dim3 grid((OUT_DIM + 127) / 128, M_BATCH / 128);  // (4, 32)
        spike_gemm2x_kernel<128><<<grid, 128>>>(s1, W2, out, OUT_DIM, FEAT);
    }
}